// round 2
// baseline (speedup 1.0000x reference)
#include <cuda_runtime.h>
#include <cstddef>

#define NN 50000
#define FIN 128
#define H1 100
#define H2 200
#define FOUT 16

// -------- scratch (static device globals; no allocation) --------
__device__ __align__(16) int   g_deg[NN];
__device__ __align__(16) float g_dis[NN];
__device__ __align__(16) float g_xw1[(size_t)NN * H1];
__device__ __align__(16) float g_agg1[(size_t)NN * H1];
__device__ __align__(16) float g_xw2[(size_t)NN * H2];
__device__ __align__(16) float g_agg2[(size_t)NN * H2];

// -------- degree / normalization --------
__global__ void k_init_deg(int n) {
    int i = blockIdx.x * blockDim.x + threadIdx.x;
    if (i < n) g_deg[i] = 1;  // self loop
}

__global__ void k_count_deg(const int* __restrict__ col, int nE) {
    int i = blockIdx.x * blockDim.x + threadIdx.x;
    if (i < nE) {
        int t = col[i];
        if ((unsigned)t < (unsigned)NN) atomicAdd(&g_deg[t], 1);
    }
}

__global__ void k_dis(int n) {
    int i = blockIdx.x * blockDim.x + threadIdx.x;
    if (i < n) g_dis[i] = rsqrtf((float)g_deg[i]);
}

// -------- generic dense layer: out[r][j] = act(in[r]) . W[:,j] (+bias) --------
// blockDim = (N, G); each y-group handles RPB rows; block covers G*RPB rows.
template <int K, int N, int G, int RPB>
__global__ void k_dense(const float* __restrict__ in, const float* __restrict__ W,
                        const float* __restrict__ bias, float* __restrict__ out,
                        int nRows, int reluIn) {
    constexpr int ROWS = G * RPB;
    __shared__ float s_in[ROWS][K];

    int r0  = blockIdx.x * ROWS;
    int tid = threadIdx.y * N + threadIdx.x;
    int nth = N * G;

    // cooperative load of the input tile (fused input ReLU)
    for (int i = tid; i < ROWS * K; i += nth) {
        int r = i / K;
        int k = i - r * K;
        float v = 0.f;
        int gr = r0 + r;
        if (gr < nRows) v = in[(size_t)gr * K + k];
        if (reluIn) v = fmaxf(v, 0.f);
        s_in[r][k] = v;
    }
    __syncthreads();

    int j     = threadIdx.x;
    int rbase = threadIdx.y * RPB;

    float acc[RPB];
#pragma unroll
    for (int r = 0; r < RPB; r++) acc[r] = 0.f;

#pragma unroll 4
    for (int k = 0; k < K; k++) {
        float w = __ldg(&W[(size_t)k * N + j]);
#pragma unroll
        for (int r = 0; r < RPB; r++)
            acc[r] = fmaf(s_in[rbase + r][k], w, acc[r]);
    }

    float b = (bias != nullptr) ? __ldg(&bias[j]) : 0.f;
#pragma unroll
    for (int r = 0; r < RPB; r++) {
        int gr = r0 + rbase + r;
        if (gr < nRows) out[(size_t)gr * N + j] = acc[r] + b;
    }
}

// -------- aggregation init: self-loop term + bias --------
// agg[i][j] = xw[i][j] * dis[i]^2 + bias[j]
template <int N>
__global__ void k_agg_init(const float* __restrict__ xw, const float* __restrict__ bias,
                           float* __restrict__ agg, int nRows) {
    int idx = blockIdx.x * blockDim.x + threadIdx.x;
    int total = nRows * N;
    if (idx >= total) return;
    int i = idx / N;
    int j = idx - i * N;
    float d = g_dis[i];
    agg[idx] = xw[idx] * d * d + __ldg(&bias[j]);
}

// -------- edge scatter-add with v4 global reductions --------
// One thread per (edge, float4-chunk). C4 = feature_dim / 4.
template <int C4>
__global__ void k_edge_agg(const float4* __restrict__ xw4, float* __restrict__ agg,
                           const int* __restrict__ rowIdx,
                           const int* __restrict__ colIdx, int nE) {
    int idx = blockIdx.x * blockDim.x + threadIdx.x;
    int total = nE * C4;
    if (idx >= total) return;
    int e = idx / C4;
    int c = idx - e * C4;
    int r = rowIdx[e];
    int t = colIdx[e];
    if ((unsigned)r >= (unsigned)NN || (unsigned)t >= (unsigned)NN) return;
    float nrm = g_dis[r] * g_dis[t];
    float4 v = xw4[(size_t)r * C4 + c];
    float* p = agg + ((size_t)t * C4 + c) * 4;
    asm volatile("red.global.add.v4.f32 [%0], {%1,%2,%3,%4};"
                 :: "l"(p), "f"(v.x * nrm), "f"(v.y * nrm), "f"(v.z * nrm), "f"(v.w * nrm)
                 : "memory");
}

// -------- launch --------
extern "C" void kernel_launch(void* const* d_in, const int* in_sizes, int n_in,
                              void* d_out, int out_size) {
    const float* x   = (const float*)d_in[0];   // [NN, FIN]
    const int*   ei  = (const int*)d_in[1];     // [2, NE] int32 (JAX x64 disabled)
    const float* W1  = (const float*)d_in[2];
    const float* b1  = (const float*)d_in[3];
    const float* W2  = (const float*)d_in[4];
    const float* b2  = (const float*)d_in[5];
    const float* Wfc = (const float*)d_in[6];
    const float* bfc = (const float*)d_in[7];
    float*       out = (float*)d_out;

    int nN = in_sizes[0] / FIN;
    int nE = in_sizes[1] / 2;
    const int* rowI = ei;
    const int* colI = ei + nE;

    float *p_xw1, *p_agg1, *p_xw2, *p_agg2;
    cudaGetSymbolAddress((void**)&p_xw1,  g_xw1);
    cudaGetSymbolAddress((void**)&p_agg1, g_agg1);
    cudaGetSymbolAddress((void**)&p_xw2,  g_xw2);
    cudaGetSymbolAddress((void**)&p_agg2, g_agg2);

    // 1) degree (with self loops) and dis = deg^-1/2
    k_init_deg<<<(nN + 255) / 256, 256>>>(nN);
    k_count_deg<<<(nE + 255) / 256, 256>>>(colI, nE);
    k_dis<<<(nN + 255) / 256, 256>>>(nN);

    // 2) layer 1: XW1 = x @ W1
    k_dense<FIN, H1, 4, 4><<<(nN + 15) / 16, dim3(H1, 4)>>>(x, W1, nullptr, p_xw1, nN, 0);

    // 3) aggregate 1: agg1 = D^-1/2 A D^-1/2 XW1 + b1   (self loop + edges)
    {
        int total = nN * H1;
        k_agg_init<H1><<<(total + 255) / 256, 256>>>(p_xw1, b1, p_agg1, nN);
        int work = nE * (H1 / 4);
        k_edge_agg<H1 / 4><<<(work + 255) / 256, 256>>>(
            (const float4*)p_xw1, p_agg1, rowI, colI, nE);
    }

    // 4) layer 2: XW2 = relu(agg1) @ W2
    k_dense<H1, H2, 2, 8><<<(nN + 15) / 16, dim3(H2, 2)>>>(p_agg1, W2, nullptr, p_xw2, nN, 1);

    // 5) aggregate 2
    {
        int total = nN * H2;
        k_agg_init<H2><<<(total + 255) / 256, 256>>>(p_xw2, b2, p_agg2, nN);
        int work = nE * (H2 / 4);
        k_edge_agg<H2 / 4><<<(work + 255) / 256, 256>>>(
            (const float4*)p_xw2, p_agg2, rowI, colI, nE);
    }

    // 6) FC: out = relu(agg2) @ Wfc + bfc
    k_dense<H2, FOUT, 16, 2><<<(nN + 31) / 32, dim3(FOUT, 16)>>>(p_agg2, Wfc, bfc, out, nN, 1);
}

// round 3
// speedup vs baseline: 1.3443x; 1.3443x over previous
#include <cuda_runtime.h>
#include <cstddef>

#define NN 50000
#define FIN 128
#define H1 100
#define H2 200
#define FOUT 16
#define C4_H1 (H1 / 4)   // 25 float4 chunks per row

// -------- scratch (static device globals; no allocation) --------
__device__ __align__(16) int   g_deg[NN];
__device__ __align__(16) float g_dis[NN];
__device__ __align__(16) float g_y1 [(size_t)NN * H1];  // d_r * (x @ W1)
__device__ __align__(16) float g_s1 [(size_t)NN * H1];  // scatter accumulator 1
__device__ __align__(16) float g_y2 [(size_t)NN * H1];  // d_i * relu(d_i*S1 + b1)
__device__ __align__(16) float g_s2 [(size_t)NN * H1];  // scatter accumulator 2
__device__ __align__(16) float g_xw2[(size_t)NN * H2];  // (d ⊙ S2) @ W2 + b2

// -------- degree / normalization --------
__global__ void k_init_deg(int n) {
    int i = blockIdx.x * blockDim.x + threadIdx.x;
    if (i < n) g_deg[i] = 1;  // self loop
}

__global__ void k_count_deg(const int* __restrict__ col, int nE) {
    int i = blockIdx.x * blockDim.x + threadIdx.x;
    if (i < nE) {
        int t = col[i];
        if ((unsigned)t < (unsigned)NN) atomicAdd(&g_deg[t], 1);
    }
}

__global__ void k_dis(int n) {
    int i = blockIdx.x * blockDim.x + threadIdx.x;
    if (i < n) g_dis[i] = rsqrtf((float)g_deg[i]);
}

// -------- dense layer: out[r][j] = f_in(in[r]) . W[:,j] (+bias), optional out-scale --------
// IN_MODE: 0=plain, 1=relu, 2=scale by dis[row].  OUT_SCALE: multiply result by dis[row].
// blockDim = (N, G); y-group handles RPB rows. float4 LDS along k (4 FMA per LDS).
template <int K, int N, int G, int RPB, int IN_MODE, int OUT_SCALE>
__global__ void k_dense(const float* __restrict__ in, const float* __restrict__ W,
                        const float* __restrict__ bias, float* __restrict__ out,
                        float* __restrict__ out2, int nRows) {
    constexpr int ROWS = G * RPB;
    __shared__ __align__(16) float s_in[ROWS][K];

    int r0  = blockIdx.x * ROWS;
    int tid = threadIdx.y * N + threadIdx.x;
    int nth = N * G;

    for (int i = tid; i < ROWS * K; i += nth) {
        int r = i / K;
        int k = i - r * K;
        int gr = r0 + r;
        float v = 0.f;
        if (gr < nRows) {
            v = in[(size_t)gr * K + k];
            if (IN_MODE == 1) v = fmaxf(v, 0.f);
            if (IN_MODE == 2) v *= g_dis[gr];
        }
        s_in[r][k] = v;
    }
    __syncthreads();

    int j     = threadIdx.x;
    int rbase = threadIdx.y * RPB;

    float acc[RPB];
#pragma unroll
    for (int r = 0; r < RPB; r++) acc[r] = 0.f;

#pragma unroll 4
    for (int k0 = 0; k0 < K; k0 += 4) {
        float w0 = __ldg(&W[(size_t)(k0 + 0) * N + j]);
        float w1 = __ldg(&W[(size_t)(k0 + 1) * N + j]);
        float w2 = __ldg(&W[(size_t)(k0 + 2) * N + j]);
        float w3 = __ldg(&W[(size_t)(k0 + 3) * N + j]);
#pragma unroll
        for (int r = 0; r < RPB; r++) {
            float4 a = *(const float4*)&s_in[rbase + r][k0];
            acc[r] = fmaf(a.x, w0, fmaf(a.y, w1, fmaf(a.z, w2, fmaf(a.w, w3, acc[r]))));
        }
    }

    float b = (bias != nullptr) ? __ldg(&bias[j]) : 0.f;
#pragma unroll
    for (int r = 0; r < RPB; r++) {
        int gr = r0 + rbase + r;
        if (gr < nRows) {
            float v = acc[r] + b;
            if (OUT_SCALE) v *= g_dis[gr];
            out[(size_t)gr * N + j] = v;
            if (out2 != nullptr) out2[(size_t)gr * N + j] = v;
        }
    }
}

// -------- pure edge scatter-add: dst[t] += src[r], float4 chunks, no scaling --------
template <int C4>
__global__ void k_edge_agg(const float4* __restrict__ src4, float* __restrict__ dst,
                           const int* __restrict__ rowIdx,
                           const int* __restrict__ colIdx, int nE) {
    int idx = blockIdx.x * blockDim.x + threadIdx.x;
    int total = nE * C4;
    if (idx >= total) return;
    int e = idx / C4;
    int c = idx - e * C4;
    int r = rowIdx[e];
    int t = colIdx[e];
    if ((unsigned)r >= (unsigned)NN || (unsigned)t >= (unsigned)NN) return;
    float4 v = src4[(size_t)r * C4 + c];
    float* p = dst + ((size_t)t * C4 + c) * 4;
    asm volatile("red.global.add.v4.f32 [%0], {%1,%2,%3,%4};"
                 :: "l"(p), "f"(v.x), "f"(v.y), "f"(v.z), "f"(v.w)
                 : "memory");
}

// -------- mid elementwise: y2 = d * relu(d*S1 + b1); write to both y2 and s2 --------
__global__ void k_mid(const float4* __restrict__ S1, const float* __restrict__ b1,
                      float4* __restrict__ Y2, float4* __restrict__ S2, int nRows) {
    int idx = blockIdx.x * blockDim.x + threadIdx.x;
    int total = nRows * C4_H1;
    if (idx >= total) return;
    int i = idx / C4_H1;
    int c = idx - i * C4_H1;
    float d  = g_dis[i];
    float4 s = S1[idx];
    float4 b = *(const float4*)&b1[c * 4];
    float4 v;
    v.x = d * fmaxf(fmaf(d, s.x, b.x), 0.f);
    v.y = d * fmaxf(fmaf(d, s.y, b.y), 0.f);
    v.z = d * fmaxf(fmaf(d, s.z, b.z), 0.f);
    v.w = d * fmaxf(fmaf(d, s.w, b.w), 0.f);
    Y2[idx] = v;
    S2[idx] = v;
}

// -------- launch --------
extern "C" void kernel_launch(void* const* d_in, const int* in_sizes, int n_in,
                              void* d_out, int out_size) {
    const float* x   = (const float*)d_in[0];   // [NN, FIN]
    const int*   ei  = (const int*)d_in[1];     // [2, NE] int32
    const float* W1  = (const float*)d_in[2];
    const float* b1  = (const float*)d_in[3];
    const float* W2  = (const float*)d_in[4];
    const float* b2  = (const float*)d_in[5];
    const float* Wfc = (const float*)d_in[6];
    const float* bfc = (const float*)d_in[7];
    float*       out = (float*)d_out;

    int nN = in_sizes[0] / FIN;
    int nE = in_sizes[1] / 2;
    const int* rowI = ei;
    const int* colI = ei + nE;

    float *p_y1, *p_s1, *p_y2, *p_s2, *p_xw2;
    cudaGetSymbolAddress((void**)&p_y1,  g_y1);
    cudaGetSymbolAddress((void**)&p_s1,  g_s1);
    cudaGetSymbolAddress((void**)&p_y2,  g_y2);
    cudaGetSymbolAddress((void**)&p_s2,  g_s2);
    cudaGetSymbolAddress((void**)&p_xw2, g_xw2);

    // 1) degree (with self loops) and dis = deg^-1/2
    k_init_deg<<<(nN + 255) / 256, 256>>>(nN);
    k_count_deg<<<(nE + 255) / 256, 256>>>(colI, nE);
    k_dis<<<(nN + 255) / 256, 256>>>(nN);

    // 2) Y1 = d_r ⊙ (x @ W1); S1 initialized to the same (self-loop term)
    k_dense<FIN, H1, 4, 4, 0, 1><<<(nN + 15) / 16, dim3(H1, 4)>>>(
        x, W1, nullptr, p_y1, p_s1, nN);

    // 3) S1[t] += Σ_edges Y1[r]   (pure scatter, normalization factored out)
    {
        int work = nE * C4_H1;
        k_edge_agg<C4_H1><<<(work + 255) / 256, 256>>>(
            (const float4*)p_y1, p_s1, rowI, colI, nE);
    }

    // 4) Y2 = d ⊙ relu(d ⊙ S1 + b1); S2 initialized to same (layer-2 agg commuted before GEMM)
    {
        int work = nN * C4_H1;
        k_mid<<<(work + 255) / 256, 256>>>(
            (const float4*)p_s1, b1, (float4*)p_y2, (float4*)p_s2, nN);
    }

    // 5) S2[t] += Σ_edges Y2[r]   (100-wide instead of 200-wide!)
    {
        int work = nE * C4_H1;
        k_edge_agg<C4_H1><<<(work + 255) / 256, 256>>>(
            (const float4*)p_y2, p_s2, rowI, colI, nE);
    }

    // 6) XW2 = (d ⊙ S2) @ W2 + b2
    k_dense<H1, H2, 2, 8, 2, 0><<<(nN + 15) / 16, dim3(H2, 2)>>>(
        p_s2, W2, b2, p_xw2, nullptr, nN);

    // 7) out = relu(XW2) @ Wfc + bfc
    k_dense<H2, FOUT, 16, 2, 1, 0><<<(nN + 31) / 32, dim3(FOUT, 16)>>>(
        p_xw2, Wfc, bfc, out, nullptr, nN);
}